// round 14
// baseline (speedup 1.0000x reference)
#include <cuda_runtime.h>
#include <cuda_fp16.h>
#include <math.h>
#include <stdint.h>

#define NB   32
#define CIN  64
#define COUT 128
#define TT   256
#define V    25
#define ICH  32
#define P    6400          // TT*V flat positions per (n, channel)
#define EPSF 1e-5f

// ---------------------------------------------------------------------------
// Scratch (device globals: allocation-free rule)
// ---------------------------------------------------------------------------
__device__ __align__(16) float  g_resT[(size_t)NB*P*COUT]; // residual fp32 [n][p][o]
__device__ __align__(16) __half g_hT [(size_t)NB*P*COUT];  // h fp16 [n][p][c]
__device__ __align__(16) __half g_wtT[9*COUT*COUT];        // wt fp16 [dt][o][c]
__device__ float g_xm[NB*CIN*V];
__device__ float g_s[NB*ICH*V];

__device__ __forceinline__ void mma_f16(float* c, const uint32_t* a, const uint32_t* b) {
    asm volatile(
        "mma.sync.aligned.m16n8k16.row.col.f32.f16.f16.f32 "
        "{%0,%1,%2,%3}, {%4,%5,%6,%7}, {%8,%9}, {%0,%1,%2,%3};"
        : "+f"(c[0]), "+f"(c[1]), "+f"(c[2]), "+f"(c[3])
        : "r"(a[0]), "r"(a[1]), "r"(a[2]), "r"(a[3]), "r"(b[0]), "r"(b[1]));
}

__device__ __forceinline__ void cp_async16(uint32_t saddr, const void* g, uint32_t nbytes) {
    asm volatile("cp.async.cg.shared.global [%0], [%1], 16, %2;"
                 :: "r"(saddr), "l"(g), "r"(nbytes));
}
#define CP_COMMIT() asm volatile("cp.async.commit_group;" ::: "memory")
#define CP_WAIT0()  asm volatile("cp.async.wait_group 0;" ::: "memory")

__device__ __forceinline__ uint32_t s2u(const void* p) {
    return (uint32_t)__cvta_generic_to_shared(p);
}

// ---------------------------------------------------------------------------
// Kernel 1: xm[n,c,v] = mean_t x[n,c,t,v]
// ---------------------------------------------------------------------------
__global__ void k_mean(const float* __restrict__ x) {
    int b = blockIdx.x;
    const float* xp = x + (size_t)b * TT * V;
    int v = threadIdx.x & 31, tg = threadIdx.x >> 5;
    float s = 0.f;
    if (v < V) for (int t = tg; t < TT; t += 8) s += xp[t*V + v];
    __shared__ float sm[8][32];
    sm[tg][v] = s;
    __syncthreads();
    if (tg == 0 && v < V) {
        float tot = 0.f;
        #pragma unroll
        for (int g = 0; g < 8; g++) tot += sm[g][v];
        g_xm[b*V + v] = tot * (1.f / TT);
    }
}

// ---------------------------------------------------------------------------
// Kernel 2: s[n,i,v] = softmax_v( -(w2@xm + b2) )   (x1 cancels in softmax)
// ---------------------------------------------------------------------------
__global__ void k_soft(const float* __restrict__ w2, const float* __restrict__ b2) {
    int n = blockIdx.x >> 5, i = blockIdx.x & 31;
    int v = threadIdx.x;
    float z = -1e30f;
    if (v < V) {
        float acc = b2[i];
        const float* w  = w2 + i*CIN;
        const float* xm = g_xm + n*CIN*V;
        #pragma unroll 8
        for (int c = 0; c < CIN; c++) acc = fmaf(w[c], xm[c*V + v], acc);
        z = -acc;
    }
    float m = z;
    #pragma unroll
    for (int off = 16; off; off >>= 1) m = fmaxf(m, __shfl_xor_sync(~0u, m, off));
    float e = (v < V) ? expf(z - m) : 0.f;
    float ssum = e;
    #pragma unroll
    for (int off = 16; off; off >>= 1) ssum += __shfl_xor_sync(~0u, ssum, off);
    if (v < V) g_s[(n*ICH + i)*V + v] = e / ssum;
}

// ---------------------------------------------------------------------------
// Kernel 2b: wt -> [dt][o][c] fp16
// ---------------------------------------------------------------------------
__global__ void k_wprep(const float* __restrict__ wt) {
    int idx = blockIdx.x * 256 + threadIdx.x;
    if (idx >= 9*COUT*COUT) return;
    int dt = idx / (COUT*COUT), r = idx % (COUT*COUT);
    int o = r / COUT, c = r % COUT;
    g_wtT[idx] = __float2half(wt[((size_t)o*COUT + c)*9 + dt]);
}

// ---------------------------------------------------------------------------
// Kernel 3: front end (fp16 mma). Per block (n, og half, ptile of 100):
//   Y[100(pad128),192] = X^T x [w3;w4;wr](og)^T via m16n8k16 fp16;
//   epilogue (fp32) via Yt[192][101]: softmax-y1, A-mix,
//   BN1+ReLU -> g_hT (half), BNr -> g_resT (fp32).
// 256 threads = 8 warps (2M x 4N), warp tile 64x48.
// ---------------------------------------------------------------------------
#define ASH 72     // front A/B smem stride in halves: banks 4*gq+tg distinct
#define YTS 101    // Yt stride (fp32, odd -> conflict-free epilogue reads)

__global__ void __launch_bounds__(256, 2) k_front(
    const float* __restrict__ x,  const float* __restrict__ A,
    const float* __restrict__ w3, const float* __restrict__ b3,
    const float* __restrict__ w4, const float* __restrict__ b4,
    const float* __restrict__ wr, const float* __restrict__ br,
    const float* __restrict__ bn1g, const float* __restrict__ bn1b,
    const float* __restrict__ bn1m, const float* __restrict__ bn1v,
    const float* __restrict__ bnrg, const float* __restrict__ bnrb,
    const float* __restrict__ bnrm, const float* __restrict__ bnrv)
{
    extern __shared__ __align__(16) float dsm[];
    __shared__ float sA[625], ss[800];
    __shared__ float sb3[64], sb4[64], sc1[64], so1[64], scr[64], sofr[64];

    const int tid = threadIdx.x;
    const int n = blockIdx.z;
    const int og = blockIdx.y;
    const int pbase = blockIdx.x * 100;
    const int obase = og * 64;

    for (int idx = tid; idx < 625; idx += 256) sA[idx] = A[idx];
    for (int idx = tid; idx < 800; idx += 256) ss[idx] = g_s[n*800 + idx];
    if (tid < 64) {
        int o = obase + tid;
        float s1 = bn1g[o] / sqrtf(bn1v[o] + EPSF);
        sc1[tid] = s1;
        so1[tid] = bn1b[o] - bn1m[o]*s1;
        float sr = bnrg[o] / sqrtf(bnrv[o] + EPSF);
        scr[tid] = sr;
        sofr[tid] = sr*br[o] + (bnrb[o] - bnrm[o]*sr);
        sb3[tid] = b3[o];
        sb4[tid] = b4[o];
    }

    __half* As = reinterpret_cast<__half*>(dsm);   // [128][ASH]
    __half* Bs = As + 128*ASH;                     // [192][ASH]

    // stage A = X^T (transpose during store, fp16); rows 100..127 zero
    const float* xn = x + (size_t)n*CIN*P + pbase;
    for (int idx = tid; idx < 1600; idx += 256) {
        int c = idx / 25, q = idx % 25;
        float4 v = *reinterpret_cast<const float4*>(xn + (size_t)c*P + q*4);
        int r = q*4;
        As[(r+0)*ASH + c] = __float2half(v.x);
        As[(r+1)*ASH + c] = __float2half(v.y);
        As[(r+2)*ASH + c] = __float2half(v.z);
        As[(r+3)*ASH + c] = __float2half(v.w);
    }
    for (int idx = tid; idx < 28*64; idx += 256)
        As[(100 + idx/64)*ASH + (idx & 63)] = __float2half(0.f);

    // stage B (og rows of w3/w4/wr), fp16, [192][64]
    for (int idx = tid; idx < 3072; idx += 256) {
        int r = idx >> 4, q = idx & 15;
        const float* src = (r < 64)  ? (w3 + (obase + r)*64) :
                           (r < 128) ? (w4 + (obase + r - 64)*64)
                                     : (wr + (obase + r - 128)*64);
        float4 v = *reinterpret_cast<const float4*>(src + q*4);
        __half* d = &Bs[r*ASH + q*4];
        d[0] = __float2half(v.x); d[1] = __float2half(v.y);
        d[2] = __float2half(v.z); d[3] = __float2half(v.w);
    }
    __syncthreads();

    // MMA: 8 warps 2M x 4N, warp tile 64 x 48, K=64 = 4 k16 steps
    const int wid = tid >> 5, lid = tid & 31;
    const int gq = lid >> 2, tg = lid & 3;
    const int wm = wid >> 2, wn = wid & 3;

    float acc[4][6][4];
    #pragma unroll
    for (int mf = 0; mf < 4; mf++)
        #pragma unroll
        for (int nf = 0; nf < 6; nf++)
            #pragma unroll
            for (int q = 0; q < 4; q++) acc[mf][nf][q] = 0.f;

    const __half* Ab = As + (wm*64 + gq)*ASH + 2*tg;
    const __half* Bb = Bs + (wn*48 + gq)*ASH + 2*tg;
    #pragma unroll
    for (int ks = 0; ks < 4; ks++) {
        int k0 = ks*16;
        uint32_t af[4][4];
        #pragma unroll
        for (int mf = 0; mf < 4; mf++) {
            const __half* ap = Ab + mf*16*ASH + k0;
            af[mf][0] = *reinterpret_cast<const uint32_t*>(ap);
            af[mf][1] = *reinterpret_cast<const uint32_t*>(ap + 8*ASH);
            af[mf][2] = *reinterpret_cast<const uint32_t*>(ap + 8);
            af[mf][3] = *reinterpret_cast<const uint32_t*>(ap + 8*ASH + 8);
        }
        #pragma unroll
        for (int nf = 0; nf < 6; nf++) {
            const __half* bp = Bb + nf*8*ASH + k0;
            uint32_t bf[2];
            bf[0] = *reinterpret_cast<const uint32_t*>(bp);
            bf[1] = *reinterpret_cast<const uint32_t*>(bp + 8);
            #pragma unroll
            for (int mf = 0; mf < 4; mf++) mma_f16(acc[mf][nf], af[mf], bf);
        }
    }
    __syncthreads();   // staging consumed

    // frags -> Yt[192][YTS] (fp32, transposed)
    float* Yt = dsm;
    #pragma unroll
    for (int mf = 0; mf < 4; mf++) {
        int r0 = wm*64 + mf*16 + gq;
        #pragma unroll
        for (int nf = 0; nf < 6; nf++) {
            int c0 = wn*48 + nf*8 + tg*2;
            if (r0 < 100) {
                Yt[c0*YTS + r0]     = acc[mf][nf][0];
                Yt[(c0+1)*YTS + r0] = acc[mf][nf][1];
            }
            if (r0 + 8 < 100) {
                Yt[c0*YTS + r0 + 8]     = acc[mf][nf][2];
                Yt[(c0+1)*YTS + r0 + 8] = acc[mf][nf][3];
            }
        }
    }
    __syncthreads();

    // epilogue: thread = (o_local 64, t 4); direct coalesced drains
    {
        const int ol = tid & 63, t = tid >> 6;
        float p3[V], p4[V], pr[V];
        const float* y3 = Yt + ol*YTS + t*25;
        const float* y4 = Yt + (64 + ol)*YTS + t*25;
        const float* yr = Yt + (128 + ol)*YTS + t*25;
        float b4v = sb4[ol];
        #pragma unroll
        for (int v = 0; v < V; v++) {
            p3[v] = y3[v];
            p4[v] = y4[v] + b4v;
            pr[v] = yr[v];
        }
        float y1 = sb3[ol];
        const float* sv = ss + (ol & 31)*V;
        #pragma unroll
        for (int v = 0; v < V; v++) y1 = fmaf(sv[v], p3[v], y1);

        float s1 = sc1[ol], o1 = so1[ol];
        __half* hdst = g_hT + ((size_t)n*P + pbase)*COUT + obase;
        #pragma unroll 5
        for (int u = 0; u < V; u++) {
            float a = y1;
            const float* Ar = sA + u*V;
            #pragma unroll
            for (int v = 0; v < V; v++) a = fmaf(Ar[v], p4[v], a);
            float h = fmaf(s1, a, o1);
            hdst[(size_t)(t*25 + u)*COUT + ol] = __float2half(h > 0.f ? h : 0.f);
        }
        float sr = scr[ol], ofr = sofr[ol];
        float* rdst = g_resT + ((size_t)n*P + pbase)*COUT + obase;
        #pragma unroll
        for (int v = 0; v < V; v++)
            rdst[(size_t)(t*25 + v)*COUT + ol] = fmaf(sr, pr[v], ofr);
    }
}

// ---------------------------------------------------------------------------
// Kernel 4: temporal conv, 9 shifted GEMMs via m16n8k16 fp16.
// cp.async double-buffered B; epilogue: BN2 + residual (fragment space)
// + ReLU, Ds transpose, coalesced out.
// ---------------------------------------------------------------------------
#define ATH 40     // tcn A/B stride in halves: word banks 20*gq+tg distinct
#define DST 133
#define AROWS 328

__global__ void __launch_bounds__(256, 2) k_tcn_mma(
    const float* __restrict__ bt,
    const float* __restrict__ bn2g, const float* __restrict__ bn2b,
    const float* __restrict__ bn2m, const float* __restrict__ bn2v,
    float* __restrict__ out)
{
    extern __shared__ __align__(16) float dsm[];
    __half* As  = reinterpret_cast<__half*>(dsm);  // [AROWS][ATH]
    __half* Bs0 = As + AROWS*ATH;                  // [128][ATH]
    __half* Bs1 = Bs0 + 128*ATH;                   // [128][ATH]
    __shared__ float s_s2[COUT], s_o2[COUT];

    const int tid = threadIdx.x, wid = tid >> 5, lid = tid & 31;
    const int gq = lid >> 2, tg = lid & 3;
    const int wm = wid >> 1, wn = wid & 1;
    const int n = blockIdx.y;
    const int pbase = blockIdx.x * 128;

    if (tid < COUT) {
        float s2 = bn2g[tid] / sqrtf(bn2v[tid] + EPSF);
        s_s2[tid] = s2;
        s_o2[tid] = bn2b[tid] - bn2m[tid]*s2 + s2*bt[tid];
    }

    float acc[2][8][4];
    #pragma unroll
    for (int mf = 0; mf < 2; mf++)
        #pragma unroll
        for (int nf = 0; nf < 8; nf++)
            #pragma unroll
            for (int q = 0; q < 4; q++) acc[mf][nf][q] = 0.f;

    const __half* hbase = g_hT + (size_t)n * P * COUT;
    __half* bufs[2] = { Bs0, Bs1 };
    int buf = 0;

    // prefetch B(it=0): ck=0, dt=0 — 128 rows x 32 halves = 512 x 16B
    {
        #pragma unroll
        for (int i = 0; i < 2; i++) {
            int idx = tid + i*256;
            int r = idx >> 2, q = idx & 3;
            cp_async16(s2u(Bs0 + r*ATH + q*8),
                       g_wtT + (size_t)r*COUT + q*8, 16);
        }
        CP_COMMIT();
    }

    #pragma unroll 1
    for (int it = 0; it < 36; it++) {
        int ck = it / 9, dt = it % 9;

        CP_WAIT0();          // B(it) landed
        __syncthreads();     // all see B(it); prior mma done

        if (dt == 0) {
            // stage A(ck): extended tile, 328 rows x 32 halves = 1312 x 16B
            #pragma unroll 1
            for (int idx = tid; idx < AROWS*4; idx += 256) {
                int r = idx >> 2, q = idx & 3;
                int gp = pbase - 100 + r;
                uint32_t ok = ((unsigned)gp < (unsigned)P) ? 16u : 0u;
                int gpc = ok ? gp : 0;
                cp_async16(s2u(As + r*ATH + q*8),
                           hbase + (size_t)gpc*COUT + ck*32 + q*8, ok);
            }
            CP_COMMIT();
            CP_WAIT0();
            __syncthreads();
        }

        // prefetch B(it+1) into alternate buffer (overlaps mma below)
        if (it + 1 < 36) {
            int ck2 = (it + 1) / 9, dt2 = (it + 1) % 9;
            __half* bd = bufs[buf ^ 1];
            #pragma unroll
            for (int i = 0; i < 2; i++) {
                int idx = tid + i*256;
                int r = idx >> 2, q = idx & 3;
                cp_async16(s2u(bd + r*ATH + q*8),
                           g_wtT + ((size_t)dt2*COUT + r)*COUT + ck2*32 + q*8, 16);
            }
            CP_COMMIT();
        }

        const __half* Aw = As + (dt*25 + wm*32 + gq)*ATH + 2*tg;
        const __half* Bw = bufs[buf] + (wn*64 + gq)*ATH + 2*tg;
        #pragma unroll
        for (int ks = 0; ks < 2; ks++) {
            int k0 = ks*16;
            uint32_t af[2][4];
            #pragma unroll
            for (int mf = 0; mf < 2; mf++) {
                const __half* ap = Aw + mf*16*ATH + k0;
                af[mf][0] = *reinterpret_cast<const uint32_t*>(ap);
                af[mf][1] = *reinterpret_cast<const uint32_t*>(ap + 8*ATH);
                af[mf][2] = *reinterpret_cast<const uint32_t*>(ap + 8);
                af[mf][3] = *reinterpret_cast<const uint32_t*>(ap + 8*ATH + 8);
            }
            uint32_t bf[8][2];
            #pragma unroll
            for (int nf = 0; nf < 8; nf++) {
                const __half* bp = Bw + nf*8*ATH + k0;
                bf[nf][0] = *reinterpret_cast<const uint32_t*>(bp);
                bf[nf][1] = *reinterpret_cast<const uint32_t*>(bp + 8);
            }
            #pragma unroll
            for (int mf = 0; mf < 2; mf++)
                #pragma unroll
                for (int nf = 0; nf < 8; nf++)
                    mma_f16(acc[mf][nf], af[mf], bf[nf]);
        }
        buf ^= 1;
    }

    // finalize in fragment space: BN2 + residual + ReLU, transpose via Ds
    __syncthreads();
    float* Ds = dsm;   // [128 p][DST]
    const float* rT = g_resT + ((size_t)n*P + pbase)*COUT;
    #pragma unroll
    for (int mf = 0; mf < 2; mf++) {
        int r0 = wm*32 + mf*16 + gq;
        #pragma unroll
        for (int nf = 0; nf < 8; nf++) {
            int c0 = wn*64 + nf*8 + tg*2;
            float2 ra = *reinterpret_cast<const float2*>(rT + (size_t)r0*COUT + c0);
            float2 rb = *reinterpret_cast<const float2*>(rT + (size_t)(r0+8)*COUT + c0);
            float s2a = s_s2[c0], s2b = s_s2[c0+1];
            float o2a = s_o2[c0], o2b = s_o2[c0+1];
            float w00 = fmaf(s2a, acc[mf][nf][0], o2a) + ra.x;
            float w01 = fmaf(s2b, acc[mf][nf][1], o2b) + ra.y;
            float w10 = fmaf(s2a, acc[mf][nf][2], o2a) + rb.x;
            float w11 = fmaf(s2b, acc[mf][nf][3], o2b) + rb.y;
            Ds[r0*DST + c0]       = w00 > 0.f ? w00 : 0.f;
            Ds[r0*DST + c0 + 1]   = w01 > 0.f ? w01 : 0.f;
            Ds[(r0+8)*DST + c0]   = w10 > 0.f ? w10 : 0.f;
            Ds[(r0+8)*DST + c0+1] = w11 > 0.f ? w11 : 0.f;
        }
    }
    __syncthreads();

    {
        int o = tid >> 1, half = tid & 1;
        size_t gbase = ((size_t)n*COUT + o)*P + pbase + half*64;
        float4* op = reinterpret_cast<float4*>(out + gbase);
        #pragma unroll 4
        for (int j4 = 0; j4 < 16; j4++) {
            int pl = half*64 + j4*4;
            float4 w;
            w.x = Ds[(pl+0)*DST + o];
            w.y = Ds[(pl+1)*DST + o];
            w.z = Ds[(pl+2)*DST + o];
            w.w = Ds[(pl+3)*DST + o];
            op[j4] = w;
        }
    }
}

// ---------------------------------------------------------------------------
extern "C" void kernel_launch(void* const* d_in, const int* in_sizes, int n_in,
                              void* d_out, int out_size) {
    const float* x    = (const float*)d_in[0];
    const float* A    = (const float*)d_in[1];
    // d_in[2], d_in[3] = w1, b1 -- cancel in softmax
    const float* w2   = (const float*)d_in[4];
    const float* b2   = (const float*)d_in[5];
    const float* w3   = (const float*)d_in[6];
    const float* b3   = (const float*)d_in[7];
    const float* w4   = (const float*)d_in[8];
    const float* b4   = (const float*)d_in[9];
    const float* bn1g = (const float*)d_in[10];
    const float* bn1b = (const float*)d_in[11];
    const float* bn1m = (const float*)d_in[12];
    const float* bn1v = (const float*)d_in[13];
    const float* wt   = (const float*)d_in[14];
    const float* bt   = (const float*)d_in[15];
    const float* bn2g = (const float*)d_in[16];
    const float* bn2b = (const float*)d_in[17];
    const float* bn2m = (const float*)d_in[18];
    const float* bn2v = (const float*)d_in[19];
    const float* wr   = (const float*)d_in[20];
    const float* br   = (const float*)d_in[21];
    const float* bnrg = (const float*)d_in[22];
    const float* bnrb = (const float*)d_in[23];
    const float* bnrm = (const float*)d_in[24];
    const float* bnrv = (const float*)d_in[25];
    float* out = (float*)d_out;

    static const int STAGE_B = (128*ASH + 192*ASH) * 2;   // 46080 B (half)
    static const int YT_B    = 192*YTS*4;                 // 77568 B
    static const int FRONT_SMEM = (STAGE_B > YT_B ? STAGE_B : YT_B);      // 77568
    static const int TCN_STAGE_B = (AROWS*ATH + 2*128*ATH) * 2;           // 46720
    static const int DS_B = 128*DST*4;                                    // 68096
    static const int TCN_SMEM = (DS_B > TCN_STAGE_B ? DS_B : TCN_STAGE_B);
    cudaFuncSetAttribute(k_front,   cudaFuncAttributeMaxDynamicSharedMemorySize, FRONT_SMEM);
    cudaFuncSetAttribute(k_tcn_mma, cudaFuncAttributeMaxDynamicSharedMemorySize, TCN_SMEM);

    k_mean<<<NB*CIN, 256>>>(x);
    k_soft<<<NB*ICH, 32>>>(w2, b2);
    k_wprep<<<(9*COUT*COUT + 255)/256, 256>>>(wt);
    k_front<<<dim3(64, 2, NB), 256, FRONT_SMEM>>>(
        x, A, w3, b3, w4, b4, wr, br,
        bn1g, bn1b, bn1m, bn1v, bnrg, bnrb, bnrm, bnrv);
    k_tcn_mma<<<dim3(50, NB), 256, TCN_SMEM>>>(
        bt, bn2g, bn2b, bn2m, bn2v, out);
}

// round 15
// speedup vs baseline: 1.4796x; 1.4796x over previous
#include <cuda_runtime.h>
#include <cuda_fp16.h>
#include <math.h>
#include <stdint.h>

#define NB   32
#define CIN  64
#define COUT 128
#define TT   256
#define V    25
#define ICH  32
#define P    6400          // TT*V flat positions per (n, channel)
#define EPSF 1e-5f

// ---------------------------------------------------------------------------
// Scratch (device globals: allocation-free rule)
// ---------------------------------------------------------------------------
__device__ __align__(16) float  g_resT[(size_t)NB*P*COUT]; // residual fp32 [n][p][o]
__device__ __align__(16) __half g_hT [(size_t)NB*P*COUT];  // h fp16 [n][p][c]
__device__ __align__(16) __half g_wtT[9*COUT*COUT];        // wt fp16 [dt][o][c]
__device__ float g_xm[NB*CIN*V];
__device__ float g_s[NB*ICH*V];

__device__ __forceinline__ void mma_f16(float* c, const uint32_t* a, const uint32_t* b) {
    asm volatile(
        "mma.sync.aligned.m16n8k16.row.col.f32.f16.f16.f32 "
        "{%0,%1,%2,%3}, {%4,%5,%6,%7}, {%8,%9}, {%0,%1,%2,%3};"
        : "+f"(c[0]), "+f"(c[1]), "+f"(c[2]), "+f"(c[3])
        : "r"(a[0]), "r"(a[1]), "r"(a[2]), "r"(a[3]), "r"(b[0]), "r"(b[1]));
}

__device__ __forceinline__ void cp_async16(uint32_t saddr, const void* g, uint32_t nbytes) {
    asm volatile("cp.async.cg.shared.global [%0], [%1], 16, %2;"
                 :: "r"(saddr), "l"(g), "r"(nbytes));
}
#define CP_COMMIT() asm volatile("cp.async.commit_group;" ::: "memory")
#define CP_WAIT0()  asm volatile("cp.async.wait_group 0;" ::: "memory")

__device__ __forceinline__ uint32_t s2u(const void* p) {
    return (uint32_t)__cvta_generic_to_shared(p);
}

// ---------------------------------------------------------------------------
// Kernel 1: xm[n,c,v] = mean_t x[n,c,t,v]
// ---------------------------------------------------------------------------
__global__ void k_mean(const float* __restrict__ x) {
    int b = blockIdx.x;
    const float* xp = x + (size_t)b * TT * V;
    int v = threadIdx.x & 31, tg = threadIdx.x >> 5;
    float s = 0.f;
    if (v < V) for (int t = tg; t < TT; t += 8) s += xp[t*V + v];
    __shared__ float sm[8][32];
    sm[tg][v] = s;
    __syncthreads();
    if (tg == 0 && v < V) {
        float tot = 0.f;
        #pragma unroll
        for (int g = 0; g < 8; g++) tot += sm[g][v];
        g_xm[b*V + v] = tot * (1.f / TT);
    }
}

// ---------------------------------------------------------------------------
// Kernel 2: s[n,i,v] = softmax_v( -(w2@xm + b2) )   (x1 cancels in softmax)
// ---------------------------------------------------------------------------
__global__ void k_soft(const float* __restrict__ w2, const float* __restrict__ b2) {
    int n = blockIdx.x >> 5, i = blockIdx.x & 31;
    int v = threadIdx.x;
    float z = -1e30f;
    if (v < V) {
        float acc = b2[i];
        const float* w  = w2 + i*CIN;
        const float* xm = g_xm + n*CIN*V;
        #pragma unroll 8
        for (int c = 0; c < CIN; c++) acc = fmaf(w[c], xm[c*V + v], acc);
        z = -acc;
    }
    float m = z;
    #pragma unroll
    for (int off = 16; off; off >>= 1) m = fmaxf(m, __shfl_xor_sync(~0u, m, off));
    float e = (v < V) ? expf(z - m) : 0.f;
    float ssum = e;
    #pragma unroll
    for (int off = 16; off; off >>= 1) ssum += __shfl_xor_sync(~0u, ssum, off);
    if (v < V) g_s[(n*ICH + i)*V + v] = e / ssum;
}

// ---------------------------------------------------------------------------
// Kernel 2b: wt -> [dt][o][c] fp16
// ---------------------------------------------------------------------------
__global__ void k_wprep(const float* __restrict__ wt) {
    int idx = blockIdx.x * 256 + threadIdx.x;
    if (idx >= 9*COUT*COUT) return;
    int dt = idx / (COUT*COUT), r = idx % (COUT*COUT);
    int o = r / COUT, c = r % COUT;
    g_wtT[idx] = __float2half(wt[((size_t)o*COUT + c)*9 + dt]);
}

// ---------------------------------------------------------------------------
// Kernel 3: front end (fp16 mma). Per block (n, og half, ptile of 100):
//   Y[100(pad128),192] = X^T x [w3;w4;wr](og)^T via m16n8k16 fp16;
//   epilogue (fp32) via Yt[192][101]: softmax-y1, A-mix,
//   BN1+ReLU -> g_hT (half), BNr -> g_resT (fp32).
// 256 threads = 8 warps (2M x 4N), warp tile 64x48.
// ---------------------------------------------------------------------------
#define ASH 72     // front A/B smem stride in halves: banks 4*gq+tg distinct
#define YTS 101    // Yt stride (fp32, odd -> conflict-free epilogue reads)

__global__ void __launch_bounds__(256, 2) k_front(
    const float* __restrict__ x,  const float* __restrict__ A,
    const float* __restrict__ w3, const float* __restrict__ b3,
    const float* __restrict__ w4, const float* __restrict__ b4,
    const float* __restrict__ wr, const float* __restrict__ br,
    const float* __restrict__ bn1g, const float* __restrict__ bn1b,
    const float* __restrict__ bn1m, const float* __restrict__ bn1v,
    const float* __restrict__ bnrg, const float* __restrict__ bnrb,
    const float* __restrict__ bnrm, const float* __restrict__ bnrv)
{
    extern __shared__ __align__(16) float dsm[];
    __shared__ float sA[625], ss[800];
    __shared__ float sb3[64], sb4[64], sc1[64], so1[64], scr[64], sofr[64];

    const int tid = threadIdx.x;
    const int n = blockIdx.z;
    const int og = blockIdx.y;
    const int pbase = blockIdx.x * 100;
    const int obase = og * 64;

    for (int idx = tid; idx < 625; idx += 256) sA[idx] = A[idx];
    for (int idx = tid; idx < 800; idx += 256) ss[idx] = g_s[n*800 + idx];
    if (tid < 64) {
        int o = obase + tid;
        float s1 = bn1g[o] / sqrtf(bn1v[o] + EPSF);
        sc1[tid] = s1;
        so1[tid] = bn1b[o] - bn1m[o]*s1;
        float sr = bnrg[o] / sqrtf(bnrv[o] + EPSF);
        scr[tid] = sr;
        sofr[tid] = sr*br[o] + (bnrb[o] - bnrm[o]*sr);
        sb3[tid] = b3[o];
        sb4[tid] = b4[o];
    }

    __half* As = reinterpret_cast<__half*>(dsm);   // [128][ASH]
    __half* Bs = As + 128*ASH;                     // [192][ASH]

    // stage A = X^T (transpose during store, fp16); rows 100..127 zero
    const float* xn = x + (size_t)n*CIN*P + pbase;
    for (int idx = tid; idx < 1600; idx += 256) {
        int c = idx / 25, q = idx % 25;
        float4 v = *reinterpret_cast<const float4*>(xn + (size_t)c*P + q*4);
        int r = q*4;
        As[(r+0)*ASH + c] = __float2half(v.x);
        As[(r+1)*ASH + c] = __float2half(v.y);
        As[(r+2)*ASH + c] = __float2half(v.z);
        As[(r+3)*ASH + c] = __float2half(v.w);
    }
    for (int idx = tid; idx < 28*64; idx += 256)
        As[(100 + idx/64)*ASH + (idx & 63)] = __float2half(0.f);

    // stage B (og rows of w3/w4/wr), fp16, [192][64]
    for (int idx = tid; idx < 3072; idx += 256) {
        int r = idx >> 4, q = idx & 15;
        const float* src = (r < 64)  ? (w3 + (obase + r)*64) :
                           (r < 128) ? (w4 + (obase + r - 64)*64)
                                     : (wr + (obase + r - 128)*64);
        float4 v = *reinterpret_cast<const float4*>(src + q*4);
        __half* d = &Bs[r*ASH + q*4];
        d[0] = __float2half(v.x); d[1] = __float2half(v.y);
        d[2] = __float2half(v.z); d[3] = __float2half(v.w);
    }
    __syncthreads();

    // MMA: 8 warps 2M x 4N, warp tile 64 x 48, K=64 = 4 k16 steps
    const int wid = tid >> 5, lid = tid & 31;
    const int gq = lid >> 2, tg = lid & 3;
    const int wm = wid >> 2, wn = wid & 3;

    float acc[4][6][4];
    #pragma unroll
    for (int mf = 0; mf < 4; mf++)
        #pragma unroll
        for (int nf = 0; nf < 6; nf++)
            #pragma unroll
            for (int q = 0; q < 4; q++) acc[mf][nf][q] = 0.f;

    const __half* Ab = As + (wm*64 + gq)*ASH + 2*tg;
    const __half* Bb = Bs + (wn*48 + gq)*ASH + 2*tg;
    #pragma unroll
    for (int ks = 0; ks < 4; ks++) {
        int k0 = ks*16;
        uint32_t af[4][4];
        #pragma unroll
        for (int mf = 0; mf < 4; mf++) {
            const __half* ap = Ab + mf*16*ASH + k0;
            af[mf][0] = *reinterpret_cast<const uint32_t*>(ap);
            af[mf][1] = *reinterpret_cast<const uint32_t*>(ap + 8*ASH);
            af[mf][2] = *reinterpret_cast<const uint32_t*>(ap + 8);
            af[mf][3] = *reinterpret_cast<const uint32_t*>(ap + 8*ASH + 8);
        }
        #pragma unroll
        for (int nf = 0; nf < 6; nf++) {
            const __half* bp = Bb + nf*8*ASH + k0;
            uint32_t bf[2];
            bf[0] = *reinterpret_cast<const uint32_t*>(bp);
            bf[1] = *reinterpret_cast<const uint32_t*>(bp + 8);
            #pragma unroll
            for (int mf = 0; mf < 4; mf++) mma_f16(acc[mf][nf], af[mf], bf);
        }
    }
    __syncthreads();   // staging consumed

    // frags -> Yt[192][YTS] (fp32, transposed)
    float* Yt = dsm;
    #pragma unroll
    for (int mf = 0; mf < 4; mf++) {
        int r0 = wm*64 + mf*16 + gq;
        #pragma unroll
        for (int nf = 0; nf < 6; nf++) {
            int c0 = wn*48 + nf*8 + tg*2;
            if (r0 < 100) {
                Yt[c0*YTS + r0]     = acc[mf][nf][0];
                Yt[(c0+1)*YTS + r0] = acc[mf][nf][1];
            }
            if (r0 + 8 < 100) {
                Yt[c0*YTS + r0 + 8]     = acc[mf][nf][2];
                Yt[(c0+1)*YTS + r0 + 8] = acc[mf][nf][3];
            }
        }
    }
    __syncthreads();

    // epilogue: thread = (o_local 64, t 4); direct coalesced drains
    {
        const int ol = tid & 63, t = tid >> 6;
        float p3[V], p4[V], pr[V];
        const float* y3 = Yt + ol*YTS + t*25;
        const float* y4 = Yt + (64 + ol)*YTS + t*25;
        const float* yr = Yt + (128 + ol)*YTS + t*25;
        float b4v = sb4[ol];
        #pragma unroll
        for (int v = 0; v < V; v++) {
            p3[v] = y3[v];
            p4[v] = y4[v] + b4v;
            pr[v] = yr[v];
        }
        float y1 = sb3[ol];
        const float* sv = ss + (ol & 31)*V;
        #pragma unroll
        for (int v = 0; v < V; v++) y1 = fmaf(sv[v], p3[v], y1);

        float s1 = sc1[ol], o1 = so1[ol];
        __half* hdst = g_hT + ((size_t)n*P + pbase)*COUT + obase;
        #pragma unroll 5
        for (int u = 0; u < V; u++) {
            float a = y1;
            const float* Ar = sA + u*V;
            #pragma unroll
            for (int v = 0; v < V; v++) a = fmaf(Ar[v], p4[v], a);
            float h = fmaf(s1, a, o1);
            hdst[(size_t)(t*25 + u)*COUT + ol] = __float2half(h > 0.f ? h : 0.f);
        }
        float sr = scr[ol], ofr = sofr[ol];
        float* rdst = g_resT + ((size_t)n*P + pbase)*COUT + obase;
        #pragma unroll
        for (int v = 0; v < V; v++)
            rdst[(size_t)(t*25 + v)*COUT + ol] = fmaf(sr, pr[v], ofr);
    }
}

// ---------------------------------------------------------------------------
// Kernel 4: temporal conv, 9 shifted GEMMs via m16n8k16 fp16.
// cp.async double-buffered B; epilogue: BN2 + residual (fragment space)
// + ReLU, Ds transpose, coalesced out.
// ---------------------------------------------------------------------------
#define ATH 40     // tcn A/B stride in halves: word banks 20*gq+tg distinct
#define DST 133
#define AROWS 328

__global__ void __launch_bounds__(256, 2) k_tcn_mma(
    const float* __restrict__ bt,
    const float* __restrict__ bn2g, const float* __restrict__ bn2b,
    const float* __restrict__ bn2m, const float* __restrict__ bn2v,
    float* __restrict__ out)
{
    extern __shared__ __align__(16) float dsm[];
    __half* As  = reinterpret_cast<__half*>(dsm);  // [AROWS][ATH]
    __half* Bs0 = As + AROWS*ATH;                  // [128][ATH]
    __half* Bs1 = Bs0 + 128*ATH;                   // [128][ATH]
    __shared__ float s_s2[COUT], s_o2[COUT];

    const int tid = threadIdx.x, wid = tid >> 5, lid = tid & 31;
    const int gq = lid >> 2, tg = lid & 3;
    const int wm = wid >> 1, wn = wid & 1;
    const int n = blockIdx.y;
    const int pbase = blockIdx.x * 128;

    if (tid < COUT) {
        float s2 = bn2g[tid] / sqrtf(bn2v[tid] + EPSF);
        s_s2[tid] = s2;
        s_o2[tid] = bn2b[tid] - bn2m[tid]*s2 + s2*bt[tid];
    }

    float acc[2][8][4];
    #pragma unroll
    for (int mf = 0; mf < 2; mf++)
        #pragma unroll
        for (int nf = 0; nf < 8; nf++)
            #pragma unroll
            for (int q = 0; q < 4; q++) acc[mf][nf][q] = 0.f;

    const __half* hbase = g_hT + (size_t)n * P * COUT;
    __half* bufs[2] = { Bs0, Bs1 };
    int buf = 0;

    // prefetch B(it=0): ck=0, dt=0 — 128 rows x 32 halves = 512 x 16B
    {
        #pragma unroll
        for (int i = 0; i < 2; i++) {
            int idx = tid + i*256;
            int r = idx >> 2, q = idx & 3;
            cp_async16(s2u(Bs0 + r*ATH + q*8),
                       g_wtT + (size_t)r*COUT + q*8, 16);
        }
        CP_COMMIT();
    }

    #pragma unroll 1
    for (int it = 0; it < 36; it++) {
        int ck = it / 9, dt = it % 9;

        CP_WAIT0();          // B(it) landed
        __syncthreads();     // all see B(it); prior mma done

        if (dt == 0) {
            // stage A(ck): extended tile, 328 rows x 32 halves = 1312 x 16B
            #pragma unroll 1
            for (int idx = tid; idx < AROWS*4; idx += 256) {
                int r = idx >> 2, q = idx & 3;
                int gp = pbase - 100 + r;
                uint32_t ok = ((unsigned)gp < (unsigned)P) ? 16u : 0u;
                int gpc = ok ? gp : 0;
                cp_async16(s2u(As + r*ATH + q*8),
                           hbase + (size_t)gpc*COUT + ck*32 + q*8, ok);
            }
            CP_COMMIT();
            CP_WAIT0();
            __syncthreads();
        }

        // prefetch B(it+1) into alternate buffer (overlaps mma below)
        if (it + 1 < 36) {
            int ck2 = (it + 1) / 9, dt2 = (it + 1) % 9;
            __half* bd = bufs[buf ^ 1];
            #pragma unroll
            for (int i = 0; i < 2; i++) {
                int idx = tid + i*256;
                int r = idx >> 2, q = idx & 3;
                cp_async16(s2u(bd + r*ATH + q*8),
                           g_wtT + ((size_t)dt2*COUT + r)*COUT + ck2*32 + q*8, 16);
            }
            CP_COMMIT();
        }

        const __half* Aw = As + (dt*25 + wm*32 + gq)*ATH + 2*tg;
        const __half* Bw = bufs[buf] + (wn*64 + gq)*ATH + 2*tg;
        #pragma unroll
        for (int ks = 0; ks < 2; ks++) {
            int k0 = ks*16;
            uint32_t af[2][4];
            #pragma unroll
            for (int mf = 0; mf < 2; mf++) {
                const __half* ap = Aw + mf*16*ATH + k0;
                af[mf][0] = *reinterpret_cast<const uint32_t*>(ap);
                af[mf][1] = *reinterpret_cast<const uint32_t*>(ap + 8*ATH);
                af[mf][2] = *reinterpret_cast<const uint32_t*>(ap + 8);
                af[mf][3] = *reinterpret_cast<const uint32_t*>(ap + 8*ATH + 8);
            }
            uint32_t bf[8][2];
            #pragma unroll
            for (int nf = 0; nf < 8; nf++) {
                const __half* bp = Bw + nf*8*ATH + k0;
                bf[nf][0] = *reinterpret_cast<const uint32_t*>(bp);
                bf[nf][1] = *reinterpret_cast<const uint32_t*>(bp + 8);
            }
            #pragma unroll
            for (int mf = 0; mf < 2; mf++)
                #pragma unroll
                for (int nf = 0; nf < 8; nf++)
                    mma_f16(acc[mf][nf], af[mf], bf[nf]);
        }
        buf ^= 1;
    }

    // finalize in fragment space: BN2 + residual + ReLU, transpose via Ds
    __syncthreads();
    float* Ds = dsm;   // [128 p][DST]
    const float* rT = g_resT + ((size_t)n*P + pbase)*COUT;
    #pragma unroll
    for (int mf = 0; mf < 2; mf++) {
        int r0 = wm*32 + mf*16 + gq;
        #pragma unroll
        for (int nf = 0; nf < 8; nf++) {
            int c0 = wn*64 + nf*8 + tg*2;
            float2 ra = *reinterpret_cast<const float2*>(rT + (size_t)r0*COUT + c0);
            float2 rb = *reinterpret_cast<const float2*>(rT + (size_t)(r0+8)*COUT + c0);
            float s2a = s_s2[c0], s2b = s_s2[c0+1];
            float o2a = s_o2[c0], o2b = s_o2[c0+1];
            float w00 = fmaf(s2a, acc[mf][nf][0], o2a) + ra.x;
            float w01 = fmaf(s2b, acc[mf][nf][1], o2b) + ra.y;
            float w10 = fmaf(s2a, acc[mf][nf][2], o2a) + rb.x;
            float w11 = fmaf(s2b, acc[mf][nf][3], o2b) + rb.y;
            Ds[r0*DST + c0]       = w00 > 0.f ? w00 : 0.f;
            Ds[r0*DST + c0 + 1]   = w01 > 0.f ? w01 : 0.f;
            Ds[(r0+8)*DST + c0]   = w10 > 0.f ? w10 : 0.f;
            Ds[(r0+8)*DST + c0+1] = w11 > 0.f ? w11 : 0.f;
        }
    }
    __syncthreads();

    {
        int o = tid >> 1, half = tid & 1;
        size_t gbase = ((size_t)n*COUT + o)*P + pbase + half*64;
        float4* op = reinterpret_cast<float4*>(out + gbase);
        #pragma unroll 4
        for (int j4 = 0; j4 < 16; j4++) {
            int pl = half*64 + j4*4;
            float4 w;
            w.x = Ds[(pl+0)*DST + o];
            w.y = Ds[(pl+1)*DST + o];
            w.z = Ds[(pl+2)*DST + o];
            w.w = Ds[(pl+3)*DST + o];
            op[j4] = w;
        }
    }
}

// ---------------------------------------------------------------------------
extern "C" void kernel_launch(void* const* d_in, const int* in_sizes, int n_in,
                              void* d_out, int out_size) {
    const float* x    = (const float*)d_in[0];
    const float* A    = (const float*)d_in[1];
    // d_in[2], d_in[3] = w1, b1 -- cancel in softmax
    const float* w2   = (const float*)d_in[4];
    const float* b2   = (const float*)d_in[5];
    const float* w3   = (const float*)d_in[6];
    const float* b3   = (const float*)d_in[7];
    const float* w4   = (const float*)d_in[8];
    const float* b4   = (const float*)d_in[9];
    const float* bn1g = (const float*)d_in[10];
    const float* bn1b = (const float*)d_in[11];
    const float* bn1m = (const float*)d_in[12];
    const float* bn1v = (const float*)d_in[13];
    const float* wt   = (const float*)d_in[14];
    const float* bt   = (const float*)d_in[15];
    const float* bn2g = (const float*)d_in[16];
    const float* bn2b = (const float*)d_in[17];
    const float* bn2m = (const float*)d_in[18];
    const float* bn2v = (const float*)d_in[19];
    const float* wr   = (const float*)d_in[20];
    const float* br   = (const float*)d_in[21];
    const float* bnrg = (const float*)d_in[22];
    const float* bnrb = (const float*)d_in[23];
    const float* bnrm = (const float*)d_in[24];
    const float* bnrv = (const float*)d_in[25];
    float* out = (float*)d_out;

    static const int STAGE_B = (128*ASH + 192*ASH) * 2;   // 46080 B (half)
    static const int YT_B    = 192*YTS*4;                 // 77568 B
    static const int FRONT_SMEM = (STAGE_B > YT_B ? STAGE_B : YT_B);      // 77568
    static const int TCN_STAGE_B = (AROWS*ATH + 2*128*ATH) * 2;           // 46720
    static const int DS_B = 128*DST*4;                                    // 68096
    static const int TCN_SMEM = (DS_B > TCN_STAGE_B ? DS_B : TCN_STAGE_B);
    cudaFuncSetAttribute(k_front,   cudaFuncAttributeMaxDynamicSharedMemorySize, FRONT_SMEM);
    cudaFuncSetAttribute(k_tcn_mma, cudaFuncAttributeMaxDynamicSharedMemorySize, TCN_SMEM);

    k_mean<<<NB*CIN, 256>>>(x);
    k_soft<<<NB*ICH, 32>>>(w2, b2);
    k_wprep<<<(9*COUT*COUT + 255)/256, 256>>>(wt);
    k_front<<<dim3(64, 2, NB), 256, FRONT_SMEM>>>(
        x, A, w3, b3, w4, b4, wr, br,
        bn1g, bn1b, bn1m, bn1v, bnrg, bnrb, bnrm, bnrv);
    k_tcn_mma<<<dim3(50, NB), 256, TCN_SMEM>>>(
        bt, bn2g, bn2b, bn2m, bn2v, out);
}